// round 1
// baseline (speedup 1.0000x reference)
#include <cuda_runtime.h>

// Problem constants
#define T_DIM   64
#define NCH     2048
#define KDIM    65536
#define THRESHV 16384.0f
#define KWTA    16

// GEMM tiling
#define BN      128            // n-columns per block tile
#define SPLITK  32             // K split factor
#define KRANGE  (KDIM / SPLITK)  // 2048 K per block
#define KT      16             // K per smem stage

// Static scratch (no allocations allowed)
__device__ float g_partial[SPLITK][T_DIM * NCH];   // 16 MB
__device__ float g_pot[T_DIM * NCH];               // 512 KB (raw GEMM out)
__device__ float g_coef[NCH];

// ---------------------------------------------------------------------------
// Kernel 1: fp32 split-K GEMM.  out[t][n] = sum_k rec[t][k] * w[n][k]
// Block tile: 64 t x 128 n, K range = 2048 per block, staged KT=16 via smem.
// Thread micro-tile: 8 t x 4 n (ty = tid>>5 in [0,8), tx = tid&31 in [0,32)).
// ---------------------------------------------------------------------------
__global__ void __launch_bounds__(256)
gemm_kernel(const float* __restrict__ rec, const float* __restrict__ w) {
    __shared__ __align__(16) float As[KT][68];    // [kk][t], padded
    __shared__ __align__(16) float Bs[KT][132];   // [kk][n], padded

    const int tid = threadIdx.x;
    const int n0  = blockIdx.x * BN;
    const int k0  = blockIdx.y * KRANGE;

    // A loader mapping: 64 t x 16 kk = 1024 floats / 256 thr = 4 (one float4)
    const int a_t  = tid >> 2;          // 0..63
    const int a_q  = (tid & 3) * 4;     // kk base 0,4,8,12
    // B loader mapping: 128 n x 16 kk = 2048 floats / 256 thr = 8 (two float4)
    const int b_n  = tid >> 1;          // 0..127
    const int b_q  = (tid & 1) * 8;     // kk base 0,8

    const float* arow = rec + (size_t)a_t * KDIM + k0 + a_q;
    const float* brow = w   + (size_t)(n0 + b_n) * KDIM + k0 + b_q;

    const int ty = tid >> 5;            // 0..7  -> t rows ty*8 .. +7
    const int tx = tid & 31;            // 0..31 -> n cols tx*4 .. +3

    float acc[8][4];
    #pragma unroll
    for (int i = 0; i < 8; i++)
        #pragma unroll
        for (int j = 0; j < 4; j++) acc[i][j] = 0.0f;

    for (int kt = 0; kt < KRANGE; kt += KT) {
        // Stage loads (transposed scatter into [kk][.] layout)
        float4 av = *(const float4*)(arow + kt);
        As[a_q + 0][a_t] = av.x;
        As[a_q + 1][a_t] = av.y;
        As[a_q + 2][a_t] = av.z;
        As[a_q + 3][a_t] = av.w;

        float4 bv0 = *(const float4*)(brow + kt);
        float4 bv1 = *(const float4*)(brow + kt + 4);
        Bs[b_q + 0][b_n] = bv0.x;
        Bs[b_q + 1][b_n] = bv0.y;
        Bs[b_q + 2][b_n] = bv0.z;
        Bs[b_q + 3][b_n] = bv0.w;
        Bs[b_q + 4][b_n] = bv1.x;
        Bs[b_q + 5][b_n] = bv1.y;
        Bs[b_q + 6][b_n] = bv1.z;
        Bs[b_q + 7][b_n] = bv1.w;

        __syncthreads();

        #pragma unroll
        for (int kk = 0; kk < KT; kk++) {
            float4 a0 = *(const float4*)&As[kk][ty * 8];
            float4 a1 = *(const float4*)&As[kk][ty * 8 + 4];
            float4 b  = *(const float4*)&Bs[kk][tx * 4];
            float aa[8] = {a0.x, a0.y, a0.z, a0.w, a1.x, a1.y, a1.z, a1.w};
            float bb[4] = {b.x, b.y, b.z, b.w};
            #pragma unroll
            for (int i = 0; i < 8; i++)
                #pragma unroll
                for (int j = 0; j < 4; j++)
                    acc[i][j] = fmaf(aa[i], bb[j], acc[i][j]);
        }
        __syncthreads();
    }

    float* outp = g_partial[blockIdx.y];
    #pragma unroll
    for (int i = 0; i < 8; i++) {
        int t = ty * 8 + i;
        #pragma unroll
        for (int j = 0; j < 4; j++)
            outp[t * NCH + n0 + tx * 4 + j] = acc[i][j];
    }
}

// ---------------------------------------------------------------------------
// Kernel 2: reduce split-K partials -> g_pot (raw potentials, pre-threshold)
// ---------------------------------------------------------------------------
__global__ void reduce_kernel() {
    int i = blockIdx.x * blockDim.x + threadIdx.x;
    if (i < T_DIM * NCH) {
        float s = 0.0f;
        #pragma unroll
        for (int p = 0; p < SPLITK; p++) s += g_partial[p][i];
        g_pot[i] = s;
    }
}

// ---------------------------------------------------------------------------
// Kernel 3: single-block winner selection, faithful to the reference:
//   pot = (out > THRESH) ? out : 0 ; spikes = sign(pot)
//   n_spk = sum_t spikes ; first_idx = clip(T - n_spk, 0, T-1)
//   first_pot = pot[first_idx] ; trunc = spikes * first_pot
//   v = trunc.max() * T ; total = sum_t (trunc + spikes*v)
//   top-16 of total (tie -> lowest index), coef = (top_val > 0)
// ---------------------------------------------------------------------------
__global__ void __launch_bounds__(1024)
winners_kernel() {
    __shared__ int   cnt_s[NCH];
    __shared__ float fpv_s[NCH];
    __shared__ float tot_s[NCH];
    __shared__ float rv[1024];
    __shared__ int   ri[1024];

    const int tid = threadIdx.x;

    // Per-column stats
    for (int k = tid; k < NCH; k += 1024) {
        int cnt = 0;
        for (int t = 0; t < T_DIM; t++) {
            float o = g_pot[t * NCH + k];
            if (o > THRESHV) cnt++;
        }
        int fi = T_DIM - cnt;
        if (fi > T_DIM - 1) fi = T_DIM - 1;
        if (fi < 0) fi = 0;
        float o  = g_pot[fi * NCH + k];
        float fp = (o > THRESHV) ? o : 0.0f;
        cnt_s[k] = cnt;
        fpv_s[k] = fp;
    }
    __syncthreads();

    // v = max over (t,k) of trunc, times T.  trunc max per column = fp if cnt>0.
    float m = 0.0f;
    for (int k = tid; k < NCH; k += 1024)
        m = fmaxf(m, (cnt_s[k] > 0) ? fpv_s[k] : 0.0f);
    rv[tid] = m;
    __syncthreads();
    for (int s = 512; s > 0; s >>= 1) {
        if (tid < s) rv[tid] = fmaxf(rv[tid], rv[tid + s]);
        __syncthreads();
    }
    float v = rv[0] * (float)T_DIM;
    __syncthreads();

    // total[k] = fold of cnt copies of fl(fp + v)  (matches elementwise add + sum)
    for (int k = tid; k < NCH; k += 1024) {
        float term = fpv_s[k] + v;
        float s = 0.0f;
        int c = cnt_s[k];
        for (int i = 0; i < c; i++) s += term;
        tot_s[k] = s;
        g_coef[k] = 0.0f;
    }
    __syncthreads();

    // Iterative top-16 argmax, tie -> lowest index (matches lax.top_k)
    for (int it = 0; it < KWTA; it++) {
        float bv = -3.4e38f;
        int   bi = NCH;
        for (int k = tid; k < NCH; k += 1024) {
            float vv = tot_s[k];
            if (vv > bv || (vv == bv && k < bi)) { bv = vv; bi = k; }
        }
        rv[tid] = bv; ri[tid] = bi;
        __syncthreads();
        for (int s = 512; s > 0; s >>= 1) {
            if (tid < s) {
                if (rv[tid + s] > rv[tid] ||
                    (rv[tid + s] == rv[tid] && ri[tid + s] < ri[tid])) {
                    rv[tid] = rv[tid + s];
                    ri[tid] = ri[tid + s];
                }
            }
            __syncthreads();
        }
        if (tid == 0) {
            int wk = ri[0];
            if (rv[0] > 0.0f) g_coef[wk] = 1.0f;
            tot_s[wk] = -3.4e38f;
        }
        __syncthreads();
    }
}

// ---------------------------------------------------------------------------
// Kernel 4: final output = sign(pot * coef) = 1 iff out > THRESH and winner
// ---------------------------------------------------------------------------
__global__ void output_kernel(float* __restrict__ out) {
    int i = blockIdx.x * blockDim.x + threadIdx.x;
    if (i < T_DIM * NCH) {
        float o = g_pot[i];
        out[i] = (o > THRESHV && g_coef[i & (NCH - 1)] > 0.0f) ? 1.0f : 0.0f;
    }
}

// ---------------------------------------------------------------------------
extern "C" void kernel_launch(void* const* d_in, const int* in_sizes, int n_in,
                              void* d_out, int out_size) {
    const float* rec = (const float*)d_in[0];   // (64, 1, 256, 256)
    const float* w   = (const float*)d_in[1];   // (2048, 1, 256, 256)
    float* out = (float*)d_out;                 // (64, 2048, 1, 1) float32

    dim3 ggrid(NCH / BN, SPLITK);               // (16, 32) = 512 blocks
    gemm_kernel<<<ggrid, 256>>>(rec, w);
    reduce_kernel<<<(T_DIM * NCH + 255) / 256, 256>>>();
    winners_kernel<<<1, 1024>>>();
    output_kernel<<<(T_DIM * NCH + 255) / 256, 256>>>(out);
}

// round 3
// speedup vs baseline: 1.7525x; 1.7525x over previous
#include <cuda_runtime.h>
#include <cuda_bf16.h>
#include <cstdint>

// Problem constants
#define T_DIM   64
#define NCH     2048
#define KDIM    65536
#define THRESHV 16384.0f
#define KWTA    16

// GEMM config
#define SPLITK  16
#define KRANGE  (KDIM / SPLITK)   // 4096 K per CTA

// Static scratch (no allocations allowed)
__device__ float g_partial[SPLITK][T_DIM * NCH];   // 8 MB
__device__ float g_pot[T_DIM * NCH];
__device__ float g_coef[NCH];

// ---------------------------------------------------------------------------
// Register helpers
// ---------------------------------------------------------------------------
// Split float2 -> hi bf16x2 (RN, packed lo-half = v.x) + lo bf16x2 (residual).
// RN (not truncation) keeps lo zero-mean so dropping lo*lo adds no bias.
__device__ __forceinline__ void split2(float2 v, uint32_t& h, uint32_t& l) {
    asm("cvt.rn.bf16x2.f32 %0, %1, %2;" : "=r"(h) : "f"(v.y), "f"(v.x));
    float hx = __uint_as_float(h << 16);
    float hy = __uint_as_float(h & 0xFFFF0000u);
    float lx = v.x - hx;
    float ly = v.y - hy;
    asm("cvt.rn.bf16x2.f32 %0, %1, %2;" : "=r"(l) : "f"(ly), "f"(lx));
}

__device__ __forceinline__ void mma16816(float* c, const uint32_t* a,
                                         uint32_t b0, uint32_t b1) {
    asm volatile(
        "mma.sync.aligned.m16n8k16.row.col.f32.bf16.bf16.f32 "
        "{%0,%1,%2,%3}, {%4,%5,%6,%7}, {%8,%9}, {%0,%1,%2,%3};"
        : "+f"(c[0]), "+f"(c[1]), "+f"(c[2]), "+f"(c[3])
        : "r"(a[0]), "r"(a[1]), "r"(a[2]), "r"(a[3]), "r"(b0), "r"(b1));
}

// ---------------------------------------------------------------------------
// Kernel 1: bf16 HMMA split-K GEMM, 3-term error-free split.
//   g_partial[ks][t*NCH + ch] = sum_k rec[t][k] * w[ch][k]   (k in split range)
// 256 threads = 8 warps in 2(M=t) x 4(N=ch); warp tile 32t x 32ch.
// Fragments loaded straight from gmem as float2 (fragment k-pairs contiguous).
// ---------------------------------------------------------------------------
__global__ void __launch_bounds__(256, 2)
gemm_mma(const float* __restrict__ rec, const float* __restrict__ w) {
    const int tid  = threadIdx.x;
    const int wid  = tid >> 5;
    const int lane = tid & 31;
    const int g    = lane >> 2;        // fragment row group 0..7
    const int q    = lane & 3;         // fragment k quad 0..3
    const int wm   = wid >> 2;         // 0..1  (t block)
    const int wn   = wid & 3;          // 0..3  (ch block)
    const int t0   = wm * 32;
    const int n0   = blockIdx.x * 128 + wn * 32;
    const size_t k0 = (size_t)blockIdx.y * KRANGE + 2 * q;

    // A (rec) row pointers: rows t0+g, +8, +16, +24
    const float* ap0 = rec + (size_t)(t0 + g) * KDIM + k0;
    const float* ap1 = ap0 + (size_t)8  * KDIM;
    const float* ap2 = ap0 + (size_t)16 * KDIM;
    const float* ap3 = ap0 + (size_t)24 * KDIM;
    // B (weight) col pointers: channels n0 + nt*8 + g
    const float* bp0 = w + (size_t)(n0 + g) * KDIM + k0;
    const float* bp1 = bp0 + (size_t)8  * KDIM;
    const float* bp2 = bp0 + (size_t)16 * KDIM;
    const float* bp3 = bp0 + (size_t)24 * KDIM;

    float acc[2][4][4];
    #pragma unroll
    for (int m = 0; m < 2; m++)
        #pragma unroll
        for (int n = 0; n < 4; n++)
            #pragma unroll
            for (int j = 0; j < 4; j++) acc[m][n][j] = 0.0f;

    #pragma unroll 2
    for (int kk = 0; kk < KRANGE; kk += 16) {
        // ---- B fragments: 4 n-tiles x (b0 @k, b1 @k+8) ----
        float2 vb[4][2];
        vb[0][0] = *(const float2*)(bp0 + kk);
        vb[0][1] = *(const float2*)(bp0 + kk + 8);
        vb[1][0] = *(const float2*)(bp1 + kk);
        vb[1][1] = *(const float2*)(bp1 + kk + 8);
        vb[2][0] = *(const float2*)(bp2 + kk);
        vb[2][1] = *(const float2*)(bp2 + kk + 8);
        vb[3][0] = *(const float2*)(bp3 + kk);
        vb[3][1] = *(const float2*)(bp3 + kk + 8);
        // ---- A fragments: 2 m-tiles x (a0..a3) ----
        float2 va[2][4];
        va[0][0] = *(const float2*)(ap0 + kk);
        va[0][1] = *(const float2*)(ap1 + kk);
        va[0][2] = *(const float2*)(ap0 + kk + 8);
        va[0][3] = *(const float2*)(ap1 + kk + 8);
        va[1][0] = *(const float2*)(ap2 + kk);
        va[1][1] = *(const float2*)(ap3 + kk);
        va[1][2] = *(const float2*)(ap2 + kk + 8);
        va[1][3] = *(const float2*)(ap3 + kk + 8);

        uint32_t bh[4][2], bl[4][2];
        #pragma unroll
        for (int n = 0; n < 4; n++) {
            split2(vb[n][0], bh[n][0], bl[n][0]);
            split2(vb[n][1], bh[n][1], bl[n][1]);
        }
        #pragma unroll
        for (int m = 0; m < 2; m++) {
            uint32_t ah[4], al[4];
            #pragma unroll
            for (int j = 0; j < 4; j++) split2(va[m][j], ah[j], al[j]);
            #pragma unroll
            for (int n = 0; n < 4; n++) {
                mma16816(acc[m][n], ah, bh[n][0], bh[n][1]);   // hi*hi
                mma16816(acc[m][n], ah, bl[n][0], bl[n][1]);   // hi*lo
                mma16816(acc[m][n], al, bh[n][0], bh[n][1]);   // lo*hi
            }
        }
    }

    // Epilogue: c0,c1 -> row g; c2,c3 -> row g+8; cols 2q, 2q+1
    float* gp = g_partial[blockIdx.y];
    #pragma unroll
    for (int m = 0; m < 2; m++) {
        const int r0 = t0 + m * 16 + g;
        #pragma unroll
        for (int n = 0; n < 4; n++) {
            const int cb = n0 + n * 8 + 2 * q;
            *(float2*)&gp[r0 * NCH + cb]       = make_float2(acc[m][n][0], acc[m][n][1]);
            *(float2*)&gp[(r0 + 8) * NCH + cb] = make_float2(acc[m][n][2], acc[m][n][3]);
        }
    }
}

// ---------------------------------------------------------------------------
// Kernel 2: reduce split-K partials -> g_pot
// ---------------------------------------------------------------------------
__global__ void reduce_kernel() {
    int i = blockIdx.x * blockDim.x + threadIdx.x;
    if (i < T_DIM * NCH) {
        float s = 0.0f;
        #pragma unroll
        for (int p = 0; p < SPLITK; p++) s += g_partial[p][i];
        g_pot[i] = s;
    }
}

// ---------------------------------------------------------------------------
// Kernel 3: winner selection (unchanged from R1 — proven exact)
// ---------------------------------------------------------------------------
__global__ void __launch_bounds__(1024)
winners_kernel() {
    __shared__ int   cnt_s[NCH];
    __shared__ float fpv_s[NCH];
    __shared__ float tot_s[NCH];
    __shared__ float rv[1024];
    __shared__ int   ri[1024];

    const int tid = threadIdx.x;

    for (int k = tid; k < NCH; k += 1024) {
        int cnt = 0;
        for (int t = 0; t < T_DIM; t++) {
            float o = g_pot[t * NCH + k];
            if (o > THRESHV) cnt++;
        }
        int fi = T_DIM - cnt;
        if (fi > T_DIM - 1) fi = T_DIM - 1;
        if (fi < 0) fi = 0;
        float o  = g_pot[fi * NCH + k];
        float fp = (o > THRESHV) ? o : 0.0f;
        cnt_s[k] = cnt;
        fpv_s[k] = fp;
    }
    __syncthreads();

    float m = 0.0f;
    for (int k = tid; k < NCH; k += 1024)
        m = fmaxf(m, (cnt_s[k] > 0) ? fpv_s[k] : 0.0f);
    rv[tid] = m;
    __syncthreads();
    for (int s = 512; s > 0; s >>= 1) {
        if (tid < s) rv[tid] = fmaxf(rv[tid], rv[tid + s]);
        __syncthreads();
    }
    float v = rv[0] * (float)T_DIM;
    __syncthreads();

    for (int k = tid; k < NCH; k += 1024) {
        float term = fpv_s[k] + v;
        float s = 0.0f;
        int c = cnt_s[k];
        for (int i = 0; i < c; i++) s += term;
        tot_s[k] = s;
        g_coef[k] = 0.0f;
    }
    __syncthreads();

    for (int it = 0; it < KWTA; it++) {
        float bv = -3.4e38f;
        int   bi = NCH;
        for (int k = tid; k < NCH; k += 1024) {
            float vv = tot_s[k];
            if (vv > bv || (vv == bv && k < bi)) { bv = vv; bi = k; }
        }
        rv[tid] = bv; ri[tid] = bi;
        __syncthreads();
        for (int s = 512; s > 0; s >>= 1) {
            if (tid < s) {
                if (rv[tid + s] > rv[tid] ||
                    (rv[tid + s] == rv[tid] && ri[tid + s] < ri[tid])) {
                    rv[tid] = rv[tid + s];
                    ri[tid] = ri[tid + s];
                }
            }
            __syncthreads();
        }
        if (tid == 0) {
            int wk = ri[0];
            if (rv[0] > 0.0f) g_coef[wk] = 1.0f;
            tot_s[wk] = -3.4e38f;
        }
        __syncthreads();
    }
}

// ---------------------------------------------------------------------------
// Kernel 4: final spikes
// ---------------------------------------------------------------------------
__global__ void output_kernel(float* __restrict__ out) {
    int i = blockIdx.x * blockDim.x + threadIdx.x;
    if (i < T_DIM * NCH) {
        float o = g_pot[i];
        out[i] = (o > THRESHV && g_coef[i & (NCH - 1)] > 0.0f) ? 1.0f : 0.0f;
    }
}

// ---------------------------------------------------------------------------
extern "C" void kernel_launch(void* const* d_in, const int* in_sizes, int n_in,
                              void* d_out, int out_size) {
    const float* rec = (const float*)d_in[0];   // (64, 1, 256, 256)
    const float* w   = (const float*)d_in[1];   // (2048, 1, 256, 256)
    float* out = (float*)d_out;                 // (64, 2048, 1, 1) float32

    dim3 grid(NCH / 128, SPLITK);               // (16, 16) = 256 CTAs
    gemm_mma<<<grid, 256>>>(rec, w);
    reduce_kernel<<<(T_DIM * NCH + 255) / 256, 256>>>();
    winners_kernel<<<1, 1024>>>();
    output_kernel<<<(T_DIM * NCH + 255) / 256, 256>>>(out);
}

// round 4
// speedup vs baseline: 2.3623x; 1.3480x over previous
#include <cuda_runtime.h>
#include <cuda_bf16.h>
#include <cstdint>

// Problem constants
#define T_DIM   64
#define NCH     2048
#define KDIM    65536
#define THRESHV 16384.0f
#define KWTA    16

// GEMM config
#define SPLITK  16
#define KRANGE  (KDIM / SPLITK)   // 4096 K per CTA
#define BK      16
#define NIT     (KRANGE / BK)     // 256 iterations
#define STAGES  4
#define ASTRIDE 24                // floats per smem row (conflict-free pad)
#define A_STAGE_BYTES (64  * ASTRIDE * 4)   // 6144
#define B_STAGE_BYTES (128 * ASTRIDE * 4)   // 12288
#define STG_BYTES     (A_STAGE_BYTES + B_STAGE_BYTES)  // 18432
#define SMEM_TOTAL    (STAGES * STG_BYTES)             // 73728

// Static scratch (no allocations allowed)
__device__ float g_partial[SPLITK][T_DIM * NCH];   // 8 MB
__device__ float g_pot[T_DIM * NCH];
__device__ float g_coef[NCH];

// ---------------------------------------------------------------------------
// Helpers
// ---------------------------------------------------------------------------
__device__ __forceinline__ uint32_t smem_u32(const void* p) {
    uint32_t a;
    asm("{ .reg .u64 t; cvta.to.shared.u64 t, %1; cvt.u32.u64 %0, t; }"
        : "=r"(a) : "l"(p));
    return a;
}
__device__ __forceinline__ void cp16(uint32_t dst, const void* src) {
    asm volatile("cp.async.cg.shared.global [%0], [%1], 16;"
                 :: "r"(dst), "l"(src) : "memory");
}
#define CP_COMMIT() asm volatile("cp.async.commit_group;" ::: "memory")
#define CP_WAIT(n)  asm volatile("cp.async.wait_group %0;" :: "n"(n) : "memory")

// Split float2 -> hi bf16x2 (RN) + lo bf16x2 (residual). RN keeps lo zero-mean
// so the dropped lo*lo term adds no bias.
__device__ __forceinline__ void split2(float2 v, uint32_t& h, uint32_t& l) {
    asm("cvt.rn.bf16x2.f32 %0, %1, %2;" : "=r"(h) : "f"(v.y), "f"(v.x));
    float hx = __uint_as_float(h << 16);
    float hy = __uint_as_float(h & 0xFFFF0000u);
    float lx = v.x - hx;
    float ly = v.y - hy;
    asm("cvt.rn.bf16x2.f32 %0, %1, %2;" : "=r"(l) : "f"(ly), "f"(lx));
}

__device__ __forceinline__ void mma16816(float* c, const uint32_t* a,
                                         uint32_t b0, uint32_t b1) {
    asm volatile(
        "mma.sync.aligned.m16n8k16.row.col.f32.bf16.bf16.f32 "
        "{%0,%1,%2,%3}, {%4,%5,%6,%7}, {%8,%9}, {%0,%1,%2,%3};"
        : "+f"(c[0]), "+f"(c[1]), "+f"(c[2]), "+f"(c[3])
        : "r"(a[0]), "r"(a[1]), "r"(a[2]), "r"(a[3]), "r"(b0), "r"(b1));
}

// ---------------------------------------------------------------------------
// Kernel 1: bf16 HMMA split-K GEMM with 4-stage cp.async smem pipeline.
//   g_partial[ks][t*NCH + ch] = sum_k rec[t][k] * w[ch][k]
// 256 threads = 2(t) x 4(ch) warps; warp tile 32t x 32ch; CTA tile 64t x 128ch.
// ---------------------------------------------------------------------------
__global__ void __launch_bounds__(256, 2)
gemm_mma(const float* __restrict__ rec, const float* __restrict__ w) {
    extern __shared__ char sm[];
    const uint32_t sbase = smem_u32(sm);

    const int tid  = threadIdx.x;
    const int wid  = tid >> 5;
    const int lane = tid & 31;
    const int g    = lane >> 2;        // fragment row group 0..7
    const int q    = lane & 3;         // fragment k quad 0..3
    const int wm   = wid >> 2;         // 0..1  (t block)
    const int wn   = wid & 3;          // 0..3  (ch block)
    const int nblk = blockIdx.x * 128;
    const size_t k0 = (size_t)blockIdx.y * KRANGE;

    // Loader mapping
    const int lrow = tid >> 2;         // 0..63
    const int lc   = tid & 3;          // 16B chunk 0..3
    const float* aSrc  = rec + (size_t)lrow * KDIM + k0 + lc * 4;
    const float* bSrc0 = w + (size_t)(nblk + lrow) * KDIM + k0 + lc * 4;
    const float* bSrc1 = w + (size_t)(nblk + 64 + lrow) * KDIM + k0 + lc * 4;
    const uint32_t aDst  = sbase + lrow * (ASTRIDE * 4) + lc * 16;
    const uint32_t bDst0 = sbase + A_STAGE_BYTES + lrow * (ASTRIDE * 4) + lc * 16;
    const uint32_t bDst1 = bDst0 + 64 * (ASTRIDE * 4);

    // Compute-side fragment byte offsets (within a stage)
    const uint32_t aoff = (uint32_t)(wm * 32 + g) * (ASTRIDE * 4) + q * 8;
    const uint32_t boff = A_STAGE_BYTES
                        + (uint32_t)(wn * 32 + g) * (ASTRIDE * 4) + q * 8;

    float acc[2][4][4];
    #pragma unroll
    for (int m = 0; m < 2; m++)
        #pragma unroll
        for (int n = 0; n < 4; n++)
            #pragma unroll
            for (int j = 0; j < 4; j++) acc[m][n][j] = 0.0f;

    // Prologue: prefetch STAGES-1 chunks
    #pragma unroll
    for (int s = 0; s < STAGES - 1; s++) {
        const size_t kb = (size_t)s * BK;
        const uint32_t so = s * STG_BYTES;
        cp16(aDst + so,  aSrc + kb);
        cp16(bDst0 + so, bSrc0 + kb);
        cp16(bDst1 + so, bSrc1 + kb);
        CP_COMMIT();
    }

    #pragma unroll 1
    for (int it = 0; it < NIT; it++) {
        CP_WAIT(STAGES - 2);
        __syncthreads();

        // Prefetch chunk it+STAGES-1 into the buffer freed last iteration
        const int nc = it + STAGES - 1;
        if (nc < NIT) {
            const uint32_t so = (nc % STAGES) * STG_BYTES;
            const size_t kb = (size_t)nc * BK;
            cp16(aDst + so,  aSrc + kb);
            cp16(bDst0 + so, bSrc0 + kb);
            cp16(bDst1 + so, bSrc1 + kb);
        }
        CP_COMMIT();

        // Compute on buffer it % STAGES
        const char* st = sm + (it % STAGES) * STG_BYTES;

        float2 vb[4][2];
        #pragma unroll
        for (int n = 0; n < 4; n++) {
            vb[n][0] = *(const float2*)(st + boff + n * (8 * ASTRIDE * 4));
            vb[n][1] = *(const float2*)(st + boff + n * (8 * ASTRIDE * 4) + 32);
        }
        float2 va[2][4];
        #pragma unroll
        for (int m = 0; m < 2; m++) {
            const uint32_t mo = aoff + m * (16 * ASTRIDE * 4);
            va[m][0] = *(const float2*)(st + mo);
            va[m][1] = *(const float2*)(st + mo + 8 * ASTRIDE * 4);
            va[m][2] = *(const float2*)(st + mo + 32);
            va[m][3] = *(const float2*)(st + mo + 8 * ASTRIDE * 4 + 32);
        }

        uint32_t bh[4][2], bl[4][2];
        #pragma unroll
        for (int n = 0; n < 4; n++) {
            split2(vb[n][0], bh[n][0], bl[n][0]);
            split2(vb[n][1], bh[n][1], bl[n][1]);
        }
        #pragma unroll
        for (int m = 0; m < 2; m++) {
            uint32_t ah[4], al[4];
            #pragma unroll
            for (int j = 0; j < 4; j++) split2(va[m][j], ah[j], al[j]);
            #pragma unroll
            for (int n = 0; n < 4; n++) {
                mma16816(acc[m][n], ah, bh[n][0], bh[n][1]);   // hi*hi
                mma16816(acc[m][n], ah, bl[n][0], bl[n][1]);   // hi*lo
                mma16816(acc[m][n], al, bh[n][0], bh[n][1]);   // lo*hi
            }
        }
        __syncthreads();
    }

    // Epilogue: c0,c1 -> row .. ; c2,c3 -> row +8; cols 2q, 2q+1
    float* gp = g_partial[blockIdx.y];
    const int t0 = wm * 32;
    #pragma unroll
    for (int m = 0; m < 2; m++) {
        const int r0 = t0 + m * 16 + g;
        #pragma unroll
        for (int n = 0; n < 4; n++) {
            const int cb = nblk + wn * 32 + n * 8 + 2 * q;
            *(float2*)&gp[r0 * NCH + cb]       = make_float2(acc[m][n][0], acc[m][n][1]);
            *(float2*)&gp[(r0 + 8) * NCH + cb] = make_float2(acc[m][n][2], acc[m][n][3]);
        }
    }
}

// ---------------------------------------------------------------------------
// Kernel 2: reduce split-K partials -> g_pot
// ---------------------------------------------------------------------------
__global__ void reduce_kernel() {
    int i = blockIdx.x * blockDim.x + threadIdx.x;
    if (i < T_DIM * NCH) {
        float s = 0.0f;
        #pragma unroll
        for (int p = 0; p < SPLITK; p++) s += g_partial[p][i];
        g_pot[i] = s;
    }
}

// ---------------------------------------------------------------------------
// Kernel 3: winner selection (unchanged — proven exact)
// ---------------------------------------------------------------------------
__global__ void __launch_bounds__(1024)
winners_kernel() {
    __shared__ int   cnt_s[NCH];
    __shared__ float fpv_s[NCH];
    __shared__ float tot_s[NCH];
    __shared__ float rv[1024];
    __shared__ int   ri[1024];

    const int tid = threadIdx.x;

    for (int k = tid; k < NCH; k += 1024) {
        int cnt = 0;
        for (int t = 0; t < T_DIM; t++) {
            float o = g_pot[t * NCH + k];
            if (o > THRESHV) cnt++;
        }
        int fi = T_DIM - cnt;
        if (fi > T_DIM - 1) fi = T_DIM - 1;
        if (fi < 0) fi = 0;
        float o  = g_pot[fi * NCH + k];
        float fp = (o > THRESHV) ? o : 0.0f;
        cnt_s[k] = cnt;
        fpv_s[k] = fp;
    }
    __syncthreads();

    float m = 0.0f;
    for (int k = tid; k < NCH; k += 1024)
        m = fmaxf(m, (cnt_s[k] > 0) ? fpv_s[k] : 0.0f);
    rv[tid] = m;
    __syncthreads();
    for (int s = 512; s > 0; s >>= 1) {
        if (tid < s) rv[tid] = fmaxf(rv[tid], rv[tid + s]);
        __syncthreads();
    }
    float v = rv[0] * (float)T_DIM;
    __syncthreads();

    for (int k = tid; k < NCH; k += 1024) {
        float term = fpv_s[k] + v;
        float s = 0.0f;
        int c = cnt_s[k];
        for (int i = 0; i < c; i++) s += term;
        tot_s[k] = s;
        g_coef[k] = 0.0f;
    }
    __syncthreads();

    for (int it = 0; it < KWTA; it++) {
        float bv = -3.4e38f;
        int   bi = NCH;
        for (int k = tid; k < NCH; k += 1024) {
            float vv = tot_s[k];
            if (vv > bv || (vv == bv && k < bi)) { bv = vv; bi = k; }
        }
        rv[tid] = bv; ri[tid] = bi;
        __syncthreads();
        for (int s = 512; s > 0; s >>= 1) {
            if (tid < s) {
                if (rv[tid + s] > rv[tid] ||
                    (rv[tid + s] == rv[tid] && ri[tid + s] < ri[tid])) {
                    rv[tid] = rv[tid + s];
                    ri[tid] = ri[tid + s];
                }
            }
            __syncthreads();
        }
        if (tid == 0) {
            int wk = ri[0];
            if (rv[0] > 0.0f) g_coef[wk] = 1.0f;
            tot_s[wk] = -3.4e38f;
        }
        __syncthreads();
    }
}

// ---------------------------------------------------------------------------
// Kernel 4: final spikes
// ---------------------------------------------------------------------------
__global__ void output_kernel(float* __restrict__ out) {
    int i = blockIdx.x * blockDim.x + threadIdx.x;
    if (i < T_DIM * NCH) {
        float o = g_pot[i];
        out[i] = (o > THRESHV && g_coef[i & (NCH - 1)] > 0.0f) ? 1.0f : 0.0f;
    }
}

// ---------------------------------------------------------------------------
extern "C" void kernel_launch(void* const* d_in, const int* in_sizes, int n_in,
                              void* d_out, int out_size) {
    const float* rec = (const float*)d_in[0];   // (64, 1, 256, 256)
    const float* w   = (const float*)d_in[1];   // (2048, 1, 256, 256)
    float* out = (float*)d_out;                 // (64, 2048, 1, 1) float32

    cudaFuncSetAttribute(gemm_mma, cudaFuncAttributeMaxDynamicSharedMemorySize,
                         SMEM_TOTAL);
    dim3 grid(NCH / 128, SPLITK);               // (16, 16) = 256 CTAs
    gemm_mma<<<grid, 256, SMEM_TOTAL>>>(rec, w);
    reduce_kernel<<<(T_DIM * NCH + 255) / 256, 256>>>();
    winners_kernel<<<1, 1024>>>();
    output_kernel<<<(T_DIM * NCH + 255) / 256, 256>>>(out);
}